// round 5
// baseline (speedup 1.0000x reference)
#include <cuda_runtime.h>

// GraphVampNet EGNN, sm_103a. Round 5: quad-split, e1 hoist, 2-edge pairing,
// and vectorized smem round-trip (STS.128/LDS.128) replacing scalar SHFL
// broadcasts in e2/c1/node-MLP (MIO-instruction bound kernel).
// B=512 frames, N=128 nodes, K=16 neighbors (j=(i+d)&127), H=16, NL=4, NC=6.

#define B_  512
#define N_  128
#define K_  16
#define H_  16
#define NC_ 6
#define NL_ 4

#define SZ_E1 (34*16)
#define SZ_E2 (16*16)
#define SZ_N1 (32*16)
#define SZ_N2 (16*16)
#define SZ_C1 (16*16)
#define SZ_C2 (16)

#define FULL 0xffffffffu
#define HS 20   // s_h / s_y row stride (words): 16B-aligned + conflict-free
#define SS 36   // stage row stride (words): 16B-aligned + conflict-free

__device__ __forceinline__ float silu_f(float v) {
    return __fdividef(v, 1.0f + __expf(-v));   // rel err ~1e-6
}

__device__ __forceinline__ float4 ld4(const float* p) {
    return *reinterpret_cast<const float4*>(p);
}

__device__ __forceinline__ void st4(float* p, const float (&a)[4]) {
    *reinterpret_cast<float4*>(p) = make_float4(a[0], a[1], a[2], a[3]);
}

__device__ __forceinline__ void fma_q(float (&acc)[4], float s, const float* w) {
    float4 v = ld4(w);
    acc[0] = fmaf(s, v.x, acc[0]); acc[1] = fmaf(s, v.y, acc[1]);
    acc[2] = fmaf(s, v.z, acc[2]); acc[3] = fmaf(s, v.w, acc[3]);
}

__device__ __forceinline__ void load_q(float (&r)[4], const float* w) {
    float4 v = ld4(w);
    r[0] = v.x; r[1] = v.y; r[2] = v.z; r[3] = v.w;
}

__device__ __forceinline__ void load16(float (&r)[16], const float* p) {
    load_q(*reinterpret_cast<float(*)[4]>(&r[0]),  p);
    load_q(*reinterpret_cast<float(*)[4]>(&r[4]),  p + 4);
    load_q(*reinterpret_cast<float(*)[4]>(&r[8]),  p + 8);
    load_q(*reinterpret_cast<float(*)[4]>(&r[12]), p + 12);
}

__global__ void __launch_bounds__(4 * N_, 2)
egnn_kernel(const float* __restrict__ data,      // [B, N, 3+N]
            const float* __restrict__ emb_w,     // [N, H]
            const float* __restrict__ ein_w, const float* __restrict__ ein_b,
            const float* __restrict__ eout_w, const float* __restrict__ eout_b,
            const float* __restrict__ fc_w,  const float* __restrict__ fc_b,
            const float* __restrict__ e1_w,  const float* __restrict__ e1_b,
            const float* __restrict__ e2_w,  const float* __restrict__ e2_b,
            const float* __restrict__ n1_w,  const float* __restrict__ n1_b,
            const float* __restrict__ n2_w,  const float* __restrict__ n2_b,
            const float* __restrict__ c1_w,  const float* __restrict__ c1_b,
            const float* __restrict__ c2_w,
            float* __restrict__ out)             // [B, NC]
{
    const int b   = blockIdx.x;
    const int tid = threadIdx.x;
    const int i   = tid >> 2;        // node 0..127
    const int q   = tid & 3;         // lane within quad
    const int q4  = q * 4;           // output-slice base

    __shared__ __align__(16) float s_h[N_][HS];
    __shared__ __align__(16) float s_y[N_][HS];
    __shared__ __align__(16) float4 s_x4[N_];
    __shared__ __align__(16) float s_st[N_][SS];   // quad exchange: [0..15]=edge0, [16..31]=edge1

    __shared__ __align__(16) float w_e1[NL_ * SZ_E1], w_e2[NL_ * SZ_E2];
    __shared__ __align__(16) float w_n1[NL_ * SZ_N1], w_n2[NL_ * SZ_N2];
    __shared__ __align__(16) float w_c1[NL_ * SZ_C1], w_c2[NL_ * SZ_C2];
    __shared__ __align__(16) float b_e1[NL_ * 16], b_e2[NL_ * 16];
    __shared__ __align__(16) float b_n1[NL_ * 16], b_n2[NL_ * 16], b_c1[NL_ * 16];
    __shared__ __align__(16) float s_ein[16 * 16], sb_ein[16];
    __shared__ __align__(16) float s_eout[16 * 16], sb_eout[16];
    __shared__ float s_fc[16 * NC_], sb_fc[NC_];
    __shared__ float s_pool[H_];

    const int NT = 4 * N_;
    for (int t = tid; t < NL_ * SZ_E1; t += NT) w_e1[t] = e1_w[t];
    for (int t = tid; t < NL_ * SZ_E2; t += NT) w_e2[t] = e2_w[t];
    for (int t = tid; t < NL_ * SZ_N1; t += NT) w_n1[t] = n1_w[t];
    for (int t = tid; t < NL_ * SZ_N2; t += NT) w_n2[t] = n2_w[t];
    for (int t = tid; t < NL_ * SZ_C1; t += NT) w_c1[t] = c1_w[t];
    for (int t = tid; t < NL_ * SZ_C2; t += NT) w_c2[t] = c2_w[t];
    for (int t = tid; t < NL_ * 16; t += NT) {
        b_e1[t] = e1_b[t]; b_e2[t] = e2_b[t];
        b_n1[t] = n1_b[t]; b_n2[t] = n2_b[t]; b_c1[t] = c1_b[t];
    }
    for (int t = tid; t < 16 * 16; t += NT) { s_ein[t] = ein_w[t]; s_eout[t] = eout_w[t]; }
    if (tid < 16) { sb_ein[tid] = ein_b[tid]; sb_eout[tid] = eout_b[tid]; }
    for (int t = tid; t < 16 * NC_; t += NT) s_fc[t] = fc_w[t];
    if (tid < NC_) sb_fc[tid] = fc_b[tid];

    float xi0, xi1, xi2;
    {
        const float* dptr = data + ((size_t)b * N_ + i) * (3 + N_);
        xi0 = dptr[0]; xi1 = dptr[1]; xi2 = dptr[2];
    }
    __syncthreads();

    // ---- init: h = emb @ ein_w + ein_b ----
    {
        float acc[4];
        load_q(acc, sb_ein + q4);
        const float* er = emb_w + i * H_;
        #pragma unroll
        for (int k = 0; k < 16; ++k) fma_q(acc, er[k], s_ein + k * 16 + q4);
        st4(&s_h[i][q4], acc);
        if (q == 0) s_x4[i] = make_float4(xi0, xi1, xi2, 0.0f);
    }
    __syncthreads();

    // ---- E_GCL layers ----
    for (int l = 0; l < NL_; ++l) {
        const float* We1 = w_e1 + l * SZ_E1 + q4;
        const float* We2 = w_e2 + l * SZ_E2 + q4;
        const float* Wn1 = w_n1 + l * SZ_N1 + q4;
        const float* Wn2 = w_n2 + l * SZ_N2 + q4;
        const float* Wc1 = w_c1 + l * SZ_C1 + q4;

        // per-node precompute: pre = bias + e_attr row + h_i-half of e1;
        // y_i = h_i(col-half) @ We1 -> shared (read by neighbors)
        float pre[4];
        {
            float hf[16];
            load16(hf, &s_h[i][0]);
            load_q(pre, b_e1 + l * 16 + q4);
            fma_q(pre, 1.0f, We1 + 33 * 16);
            float yq[4] = {0.f, 0.f, 0.f, 0.f};
            #pragma unroll
            for (int k = 0; k < 16; ++k) {
                fma_q(pre, hf[k], We1 + k * 16);
                fma_q(yq, hf[k], We1 + (16 + k) * 16);
            }
            st4(&s_y[i][q4], yq);
        }
        __syncthreads();   // s_y visible to all

        float accm[4] = {0.f, 0.f, 0.f, 0.f};
        float ax0 = 0.f, ax1 = 0.f, ax2 = 0.f;

        #pragma unroll 1
        for (int d = 1; d <= K_; d += 2) {
            const int j0 = (i + d)     & (N_ - 1);
            const int j1 = (i + d + 1) & (N_ - 1);

            // e1 slice: a = silu(pre + rad*w32 + y_j)
            float a0[4], a1[4];
            {
                float4 xj0 = s_x4[j0];
                float4 xj1 = s_x4[j1];
                const float d00 = xi0 - xj0.x, d01 = xi1 - xj0.y, d02 = xi2 - xj0.z;
                const float d10 = xi0 - xj1.x, d11 = xi1 - xj1.y, d12 = xi2 - xj1.z;
                const float rad0 = fmaf(d00, d00, fmaf(d01, d01, d02 * d02));
                const float rad1 = fmaf(d10, d10, fmaf(d11, d11, d12 * d12));
                load_q(a0, &s_y[j0][q4]);
                load_q(a1, &s_y[j1][q4]);
                float4 w32 = ld4(We1 + 32 * 16);
                a0[0] = silu_f(fmaf(rad0, w32.x, a0[0] + pre[0]));
                a0[1] = silu_f(fmaf(rad0, w32.y, a0[1] + pre[1]));
                a0[2] = silu_f(fmaf(rad0, w32.z, a0[2] + pre[2]));
                a0[3] = silu_f(fmaf(rad0, w32.w, a0[3] + pre[3]));
                a1[0] = silu_f(fmaf(rad1, w32.x, a1[0] + pre[0]));
                a1[1] = silu_f(fmaf(rad1, w32.y, a1[1] + pre[1]));
                a1[2] = silu_f(fmaf(rad1, w32.z, a1[2] + pre[2]));
                a1[3] = silu_f(fmaf(rad1, w32.w, a1[3] + pre[3]));
            }

            // quad exchange of a (replaces 32 SHFL with 2 STS + 8 LDS)
            st4(&s_st[i][q4], a0);
            st4(&s_st[i][16 + q4], a1);
            __syncwarp();
            float af0[16], af1[16];
            load16(af0, &s_st[i][0]);
            load16(af1, &s_st[i][16]);

            // e2: m = silu(a_full @ We2 + b), weights loaded once for both edges
            float m0[4], m1[4];
            load_q(m0, b_e2 + l * 16 + q4);
            #pragma unroll
            for (int o = 0; o < 4; ++o) m1[o] = m0[o];
            #pragma unroll
            for (int k = 0; k < 16; ++k) {
                float4 w = ld4(We2 + k * 16);
                m0[0] = fmaf(af0[k], w.x, m0[0]); m0[1] = fmaf(af0[k], w.y, m0[1]);
                m0[2] = fmaf(af0[k], w.z, m0[2]); m0[3] = fmaf(af0[k], w.w, m0[3]);
                m1[0] = fmaf(af1[k], w.x, m1[0]); m1[1] = fmaf(af1[k], w.y, m1[1]);
                m1[2] = fmaf(af1[k], w.z, m1[2]); m1[3] = fmaf(af1[k], w.w, m1[3]);
            }
            #pragma unroll
            for (int o = 0; o < 4; ++o) {
                m0[o] = silu_f(m0[o]); m1[o] = silu_f(m1[o]);
                accm[o] += m0[o] + m1[o];
            }

            // quad exchange of m
            __syncwarp();                       // af reads done before overwrite
            st4(&s_st[i][q4], m0);
            st4(&s_st[i][16 + q4], m1);
            __syncwarp();
            float mf0[16], mf1[16];
            load16(mf0, &s_st[i][0]);
            load16(mf1, &s_st[i][16]);

            // coord_mlp: t = silu(m_full @ Wc1 + b) @ Wc2
            float t0a[4], t1a[4];
            load_q(t0a, b_c1 + l * 16 + q4);
            #pragma unroll
            for (int o = 0; o < 4; ++o) t1a[o] = t0a[o];
            #pragma unroll
            for (int k = 0; k < 16; ++k) {
                float4 w = ld4(Wc1 + k * 16);
                t0a[0] = fmaf(mf0[k], w.x, t0a[0]); t0a[1] = fmaf(mf0[k], w.y, t0a[1]);
                t0a[2] = fmaf(mf0[k], w.z, t0a[2]); t0a[3] = fmaf(mf0[k], w.w, t0a[3]);
                t1a[0] = fmaf(mf1[k], w.x, t1a[0]); t1a[1] = fmaf(mf1[k], w.y, t1a[1]);
                t1a[2] = fmaf(mf1[k], w.z, t1a[2]); t1a[3] = fmaf(mf1[k], w.w, t1a[3]);
            }
            float t0, t1;
            {
                float4 wc2 = ld4(w_c2 + l * SZ_C2 + q4);
                t0 = silu_f(t0a[0]) * wc2.x;
                t0 = fmaf(silu_f(t0a[1]), wc2.y, t0);
                t0 = fmaf(silu_f(t0a[2]), wc2.z, t0);
                t0 = fmaf(silu_f(t0a[3]), wc2.w, t0);
                t1 = silu_f(t1a[0]) * wc2.x;
                t1 = fmaf(silu_f(t1a[1]), wc2.y, t1);
                t1 = fmaf(silu_f(t1a[2]), wc2.z, t1);
                t1 = fmaf(silu_f(t1a[3]), wc2.w, t1);
            }
            t0 += __shfl_xor_sync(FULL, t0, 1, 4);
            t0 += __shfl_xor_sync(FULL, t0, 2, 4);
            t1 += __shfl_xor_sync(FULL, t1, 1, 4);
            t1 += __shfl_xor_sync(FULL, t1, 2, 4);

            // apply coord update contributions (re-read xj, cd recompute)
            {
                float4 xj0 = s_x4[j0];
                float4 xj1 = s_x4[j1];
                ax0 = fmaf(xi0 - xj0.x, t0, fmaf(xi0 - xj1.x, t1, ax0));
                ax1 = fmaf(xi1 - xj0.y, t0, fmaf(xi1 - xj1.y, t1, ax1));
                ax2 = fmaf(xi2 - xj0.z, t0, fmaf(xi2 - xj1.z, t1, ax2));
            }
            __syncwarp();   // mf reads done before next iteration's STS
        }

        xi0 = fmaf(ax0, 0.0625f, xi0);
        xi1 = fmaf(ax1, 0.0625f, xi1);
        xi2 = fmaf(ax2, 0.0625f, xi2);

        // node_mlp: h += silu([h, agg_m] @ n1 + b) @ n2 + b
        float hb[4];
        {
            float hf[16];
            load16(hf, &s_h[i][0]);
            float na[4];
            load_q(na, b_n1 + l * 16 + q4);
            #pragma unroll
            for (int k = 0; k < 16; ++k) fma_q(na, hf[k], Wn1 + k * 16);

            // exchange accm across quad
            st4(&s_st[i][q4], accm);
            __syncwarp();
            float xf[16];
            load16(xf, &s_st[i][0]);
            #pragma unroll
            for (int k = 0; k < 16; ++k) fma_q(na, xf[k], Wn1 + (16 + k) * 16);
            #pragma unroll
            for (int o = 0; o < 4; ++o) na[o] = silu_f(na[o]);

            // exchange na across quad
            __syncwarp();
            st4(&s_st[i][q4], na);
            __syncwarp();
            load16(xf, &s_st[i][0]);
            load_q(hb, b_n2 + l * 16 + q4);
            #pragma unroll
            for (int k = 0; k < 16; ++k) fma_q(hb, xf[k], Wn2 + k * 16);
            float hq[4];
            load_q(hq, &s_h[i][q4]);   // own residual slice
            #pragma unroll
            for (int o = 0; o < 4; ++o) hb[o] += hq[o];
        }

        __syncthreads();   // all reads of old s_h / s_x done
        st4(&s_h[i][q4], hb);
        if (q == 0) s_x4[i] = make_float4(xi0, xi1, xi2, 0.0f);
        __syncthreads();
    }

    // ---- embedding_out + pooling ----
    {
        float hf[16];
        load16(hf, &s_h[i][0]);
        float ho[4];
        load_q(ho, sb_eout + q4);
        #pragma unroll
        for (int k = 0; k < 16; ++k) fma_q(ho, hf[k], s_eout + k * 16 + q4);
        __syncthreads();
        st4(&s_h[i][q4], ho);
    }
    __syncthreads();

    if (tid < H_) {
        float s = 0.0f;
        for (int j = 0; j < N_; ++j) s += s_h[j][tid];
        s_pool[tid] = s * (1.0f / (float)N_);
    }
    __syncthreads();

    if (tid == 0) {
        float logit[NC_];
        float mx = -1e30f;
        #pragma unroll
        for (int c = 0; c < NC_; ++c) {
            float s = sb_fc[c];
            #pragma unroll
            for (int k = 0; k < H_; ++k) s = fmaf(s_pool[k], s_fc[k * NC_ + c], s);
            logit[c] = s;
            mx = fmaxf(mx, s);
        }
        float den = 0.0f;
        float e[NC_];
        #pragma unroll
        for (int c = 0; c < NC_; ++c) { e[c] = expf(logit[c] - mx); den += e[c]; }
        const float inv = 1.0f / den;
        #pragma unroll
        for (int c = 0; c < NC_; ++c) out[b * NC_ + c] = e[c] * inv;
    }
}

extern "C" void kernel_launch(void* const* d_in, const int* in_sizes, int n_in,
                              void* d_out, int out_size)
{
    const float* data   = (const float*)d_in[0];
    const float* emb_w  = (const float*)d_in[3];
    const float* ein_w  = (const float*)d_in[4];
    const float* ein_b  = (const float*)d_in[5];
    const float* eout_w = (const float*)d_in[6];
    const float* eout_b = (const float*)d_in[7];
    const float* fc_w   = (const float*)d_in[8];
    const float* fc_b   = (const float*)d_in[9];
    const float* e1_w   = (const float*)d_in[10];
    const float* e1_b   = (const float*)d_in[11];
    const float* e2_w   = (const float*)d_in[12];
    const float* e2_b   = (const float*)d_in[13];
    const float* n1_w   = (const float*)d_in[14];
    const float* n1_b   = (const float*)d_in[15];
    const float* n2_w   = (const float*)d_in[16];
    const float* n2_b   = (const float*)d_in[17];
    const float* c1_w   = (const float*)d_in[18];
    const float* c1_b   = (const float*)d_in[19];
    const float* c2_w   = (const float*)d_in[20];
    float* out = (float*)d_out;

    egnn_kernel<<<B_, 4 * N_>>>(data, emb_w, ein_w, ein_b, eout_w, eout_b,
                                fc_w, fc_b, e1_w, e1_b, e2_w, e2_b,
                                n1_w, n1_b, n2_w, n2_b, c1_w, c1_b, c2_w, out);
}